// round 11
// baseline (speedup 1.0000x reference)
#include <cuda_runtime.h>
#include <cstdint>

// EmbedSocialFeatures: 3-layer MLP (64->32->64->128, ReLU x2) + segment mean.
// R11: layer1 tf32 m16n8k8 (unchanged), layer2 fp16 m16n8k16 (half the mma +
// half the weight-frag/A/stash smem traffic); seg_out caches W3 in smem with
// 8 segs/CTA (cuts 268MB L2 reads to 33MB); vectorized zero; grid 304 (152 SMs).

#define TPB_A  256
#define GRID_A 304
#define S_TILE 68      // f32 words per tile row (conflict-free staging + frag reads)
#define ROW_B  272     // bytes per tile row

// ---- smem layout (bytes), kernel A ----
#define TU0_OFF  0          // 34816: tile buffer 0 (128 x 68 f32)
#define TU1_OFF  34816      // 34816: tile buffer 1
#define SEG0_OFF 69632      // 512
#define SEG1_OFF 70144      // 512
#define W1F_OFF  70656      // 8192: 32 tf32 B-frags x 256B
#define W2F_OFF  78848      // 4096: 16 fp16 B-frags x 256B
#define B1S_OFF  87040      // 128
#define B2S_OFF  87168      // 256
#define SMEM_A   87424      // 2 CTAs/SM

#define MAXSEG 8192
__device__ float g_acc[MAXSEG * 64];
__device__ float g_cnt[MAXSEG];

static __device__ __forceinline__ uint32_t rna_tf32(float x) {
    uint32_t r;
    asm("cvt.rna.tf32.f32 %0, %1;" : "=r"(r) : "f"(x));
    return r;
}
// pack {lo, hi} f32 -> f16x2 (cvt d,a,b: hi=cvt(a), lo=cvt(b))
static __device__ __forceinline__ uint32_t pack_h2(float lo, float hi) {
    uint32_t r;
    asm("cvt.rn.f16x2.f32 %0, %1, %2;" : "=r"(r) : "f"(hi), "f"(lo));
    return r;
}
static __device__ __forceinline__ uint32_t smem_u32(const void* p) {
    uint32_t a;
    asm("{ .reg .u64 t; cvta.to.shared.u64 t, %1; cvt.u32.u64 %0, t; }" : "=r"(a) : "l"(p));
    return a;
}
static __device__ __forceinline__ void mma8(float d[4],
                                            uint32_t a0, uint32_t a1, uint32_t a2, uint32_t a3,
                                            uint32_t b0, uint32_t b1) {
    asm volatile(
        "mma.sync.aligned.m16n8k8.row.col.f32.tf32.tf32.f32 "
        "{%0,%1,%2,%3}, {%4,%5,%6,%7}, {%8,%9}, {%0,%1,%2,%3};"
        : "+f"(d[0]), "+f"(d[1]), "+f"(d[2]), "+f"(d[3])
        : "r"(a0), "r"(a1), "r"(a2), "r"(a3), "r"(b0), "r"(b1));
}
static __device__ __forceinline__ void mma16(float d[4],
                                             uint32_t a0, uint32_t a1, uint32_t a2, uint32_t a3,
                                             uint32_t b0, uint32_t b1) {
    asm volatile(
        "mma.sync.aligned.m16n8k16.row.col.f32.f16.f16.f32 "
        "{%0,%1,%2,%3}, {%4,%5,%6,%7}, {%8,%9}, {%0,%1,%2,%3};"
        : "+f"(d[0]), "+f"(d[1]), "+f"(d[2]), "+f"(d[3])
        : "r"(a0), "r"(a1), "r"(a2), "r"(a3), "r"(b0), "r"(b1));
}
#define CP_ASYNC16(dst, src) \
    asm volatile("cp.async.cg.shared.global [%0], [%1], 16;" :: "r"(dst), "l"(src) : "memory")
#define CP_COMMIT()  asm volatile("cp.async.commit_group;" ::: "memory")
#define CP_WAIT1()   asm volatile("cp.async.wait_group 1;" ::: "memory")

// ---------------- kernel 0: zero scratch (vectorized) ----------------
__global__ void zero_kernel(int S) {
    const int i = blockIdx.x * blockDim.x + threadIdx.x;
    const float4 z = make_float4(0.f, 0.f, 0.f, 0.f);
    if (i < S * 16) reinterpret_cast<float4*>(g_acc)[i] = z;
    const int j = i - S * 16;
    if (j >= 0 && j < S / 4) reinterpret_cast<float4*>(g_cnt)[j] = z;
}

// ---------------- kernel A: persistent tile GEMM + segmented accumulate ----------------
extern __shared__ char smemA[];

static __device__ __forceinline__ void issue_tile(
    const float* __restrict__ f_all, const int* __restrict__ seg_ids, int Nrows,
    int t, int tid, uint32_t sb_tu, float* tuf, int* segs)
{
    const int base = t * 128;
    const int nrows = min(128, Nrows - base);
    const char* src = (const char*)f_all + (size_t)base * 256;
    if (nrows == 128) {
        #pragma unroll
        for (int j = 0; j < 8; j++) {
            const int i = tid + j * TPB_A;
            const int r = i >> 4, q = i & 15;
            CP_ASYNC16(sb_tu + (uint32_t)(r * ROW_B + q * 16), src + (size_t)i * 16);
        }
        if (tid < 32)
            CP_ASYNC16(smem_u32(segs) + (uint32_t)(tid * 16),
                       (const char*)(seg_ids + base) + tid * 16);
    } else {
        for (int i = tid; i < nrows * 16; i += TPB_A) {
            const int r = i >> 4, q = i & 15;
            CP_ASYNC16(sb_tu + (uint32_t)(r * ROW_B + q * 16), src + (size_t)i * 16);
        }
        for (int i = nrows * 16 + tid; i < 2048; i += TPB_A) {
            const int r = i >> 4, q = i & 15;
            *(float4*)(&tuf[r * S_TILE + q * 4]) = make_float4(0.f, 0.f, 0.f, 0.f);
        }
        for (int r = tid; r < 128; r += TPB_A)
            segs[r] = __ldg(&seg_ids[base + min(r, nrows - 1)]);
    }
}

__global__ __launch_bounds__(TPB_A, 2)
void mlp_accum_kernel(const float* __restrict__ f_all,
                      const int*   __restrict__ seg_ids, int Nrows,
                      const float* __restrict__ W1, const float* __restrict__ b1,
                      const float* __restrict__ W2, const float* __restrict__ b2)
{
    const int tid   = threadIdx.x;
    const int lane  = tid & 31;
    const int wbase = (tid >> 5) * 16;     // warp's 16 rows in tile
    const int g     = lane >> 2;
    const int tig   = lane & 3;

    float* tuf0 = (float*)(smemA + TU0_OFF);
    float* tuf1 = (float*)(smemA + TU1_OFF);
    int*   seg0 = (int*)(smemA + SEG0_OFF);
    int*   seg1 = (int*)(smemA + SEG1_OFF);
    float* b1s  = (float*)(smemA + B1S_OFF);
    float* b2s  = (float*)(smemA + B2S_OFF);
    const uint32_t sb_tu0 = smem_u32(tuf0);
    const uint32_t sb_tu1 = smem_u32(tuf1);

    const int T      = (Nrows + 127) >> 7;
    const int stride = gridDim.x;
    const int t0     = blockIdx.x;

    if (t0 < T) issue_tile(f_all, seg_ids, Nrows, t0, tid, sb_tu0, tuf0, seg0);
    CP_COMMIT();

    // ---- W1 tf32 fragments (m16n8k8): frag f=k*4+n ----
    for (int idx = tid; idx < 1024; idx += TPB_A) {
        const int f = idx >> 5, l = idx & 31;
        const int k = f >> 2, n = f & 3, gg = l >> 2, t = l & 3;
        uint2 v;
        v.x = rna_tf32(__ldg(&W1[(8 * k + t) * 32 + 8 * n + gg]));
        v.y = rna_tf32(__ldg(&W1[(8 * k + t + 4) * 32 + 8 * n + gg]));
        *(uint2*)(smemA + W1F_OFF + f * 256 + l * 8) = v;
    }
    // ---- W2 fp16 fragments (m16n8k16): frag f = ks*8 + nb, col = 8nb+g ----
    for (int idx = tid; idx < 512; idx += TPB_A) {
        const int f = idx >> 5, l = idx & 31;
        const int ks = f >> 3, nb2 = f & 7, gg = l >> 2, t = l & 3;
        const int col = 8 * nb2 + gg;
        const int k0 = 16 * ks + 2 * t;
        uint2 v;
        v.x = pack_h2(__ldg(&W2[k0 * 64 + col]),       __ldg(&W2[(k0 + 1) * 64 + col]));
        v.y = pack_h2(__ldg(&W2[(k0 + 8) * 64 + col]), __ldg(&W2[(k0 + 9) * 64 + col]));
        *(uint2*)(smemA + W2F_OFF + f * 256 + l * 8) = v;
    }
    if (tid < 32) b1s[tid] = b1[tid];
    if (tid < 64) b2s[tid] = b2[tid];
    __syncthreads();

    float b1v0[4], b1v1[4];
    #pragma unroll
    for (int n = 0; n < 4; n++) {
        b1v0[n] = b1s[8 * n + 2 * tig];
        b1v1[n] = b1s[8 * n + 2 * tig + 1];
    }

    int buf = 0;
    for (int t = t0; t < T; t += stride) {
        const int nt = t + stride;
        if (nt < T)
            issue_tile(f_all, seg_ids, Nrows, nt, tid,
                       buf ? sb_tu0 : sb_tu1, buf ? tuf0 : tuf1, buf ? seg0 : seg1);
        CP_COMMIT();
        CP_WAIT1();
        __syncthreads();

        float*    tuf    = buf ? tuf1 : tuf0;
        uint32_t* tu     = (uint32_t*)tuf;
        int*      segs   = buf ? seg1 : seg0;
        const int nrows  = min(128, Nrows - t * 128);
        const int r0     = wbase + g;

        // ---- layer 1: tf32 m16n8k8, D1[16x32] ----
        float d1[4][4];
        #pragma unroll
        for (int n = 0; n < 4; n++)
            #pragma unroll
            for (int c = 0; c < 4; c++) d1[n][c] = 0.0f;
        #pragma unroll
        for (int k = 0; k < 8; k++) {
            const uint32_t a0 = rna_tf32(tuf[r0 * S_TILE + 8 * k + tig]);
            const uint32_t a1 = rna_tf32(tuf[(r0 + 8) * S_TILE + 8 * k + tig]);
            const uint32_t a2 = rna_tf32(tuf[r0 * S_TILE + 8 * k + tig + 4]);
            const uint32_t a3 = rna_tf32(tuf[(r0 + 8) * S_TILE + 8 * k + tig + 4]);
            #pragma unroll
            for (int n = 0; n < 4; n++) {
                const uint2 bf = *(const uint2*)(smemA + W1F_OFF + (k * 4 + n) * 256 + lane * 8);
                mma8(d1[n], a0, a1, a2, a3, bf.x, bf.y);
            }
        }

        // ---- epilogue 1: h1 = f16x2(relu(d1+b1)) at pair index p=4n+tig ----
        #pragma unroll
        for (int n = 0; n < 4; n++) {
            const float v00 = fmaxf(d1[n][0] + b1v0[n], 0.0f);
            const float v01 = fmaxf(d1[n][1] + b1v1[n], 0.0f);
            const float v10 = fmaxf(d1[n][2] + b1v0[n], 0.0f);
            const float v11 = fmaxf(d1[n][3] + b1v1[n], 0.0f);
            tu[r0 * S_TILE + 4 * n + tig]       = pack_h2(v00, v01);
            tu[(r0 + 8) * S_TILE + 4 * n + tig] = pack_h2(v10, v11);
        }
        __syncwarp();

        // ---- layer 2: fp16 m16n8k16, D2[16x64], K=32 in 2 k-steps ----
        float d2[8][4];
        #pragma unroll
        for (int q = 0; q < 8; q++)
            #pragma unroll
            for (int c = 0; c < 4; c++) d2[q][c] = 0.0f;
        #pragma unroll
        for (int ks = 0; ks < 2; ks++) {
            const uint32_t a0 = tu[r0 * S_TILE + 8 * ks + tig];
            const uint32_t a1 = tu[(r0 + 8) * S_TILE + 8 * ks + tig];
            const uint32_t a2 = tu[r0 * S_TILE + 8 * ks + tig + 4];
            const uint32_t a3 = tu[(r0 + 8) * S_TILE + 8 * ks + tig + 4];
            #pragma unroll
            for (int q = 0; q < 8; q++) {
                const uint2 bf = *(const uint2*)(smemA + W2F_OFF + (ks * 8 + q) * 256 + lane * 8);
                mma16(d2[q], a0, a1, a2, a3, bf.x, bf.y);
            }
        }

        // ---- epilogue 2: masked relu(h2) f32 stash over own rows ----
        {
            const float m0 = (r0 < nrows) ? 1.0f : 0.0f;
            const float m1 = (r0 + 8 < nrows) ? 1.0f : 0.0f;
            #pragma unroll
            for (int q = 0; q < 8; q++) {
                const int c = 8 * q + 2 * tig;
                const float bv0 = b2s[c], bv1 = b2s[c + 1];
                float2 v0, v1;
                v0.x = m0 * fmaxf(d2[q][0] + bv0, 0.0f);
                v0.y = m0 * fmaxf(d2[q][1] + bv1, 0.0f);
                v1.x = m1 * fmaxf(d2[q][2] + bv0, 0.0f);
                v1.y = m1 * fmaxf(d2[q][3] + bv1, 0.0f);
                *(float2*)(&tuf[r0 * S_TILE + c]) = v0;
                *(float2*)(&tuf[(r0 + 8) * S_TILE + c]) = v1;
            }
        }
        __syncthreads();

        // ---- segmented run-scan: quarter q rows [32q,32q+32), column c ----
        {
            const int q = tid >> 6, c = tid & 63;
            const int rq = q * 32;
            int cur = segs[rq];
            float run = 0.0f, crun = 0.0f;
            #pragma unroll 4
            for (int r = rq; r < rq + 32; r++) {
                const int sg = segs[r];
                if (sg != cur) {
                    atomicAdd(&g_acc[cur * 64 + c], run);
                    if (c == 0) atomicAdd(&g_cnt[cur], crun);
                    run = 0.0f; crun = 0.0f; cur = sg;
                }
                run += tuf[r * S_TILE + c];
                if (r < nrows) crun += 1.0f;
            }
            atomicAdd(&g_acc[cur * 64 + c], run);
            if (c == 0) atomicAdd(&g_cnt[cur], crun);
        }
        __syncthreads();
        buf ^= 1;
    }
}

// ---------------- kernel B: per-segment mean @ W3 + b3 (W3 smem-cached) ----------------
#define SEG_PER_CTA 8
__global__ __launch_bounds__(128)
void seg_out_kernel(const float* __restrict__ W3, const float* __restrict__ b3,
                    float* __restrict__ out, int S)
{
    __shared__ float w3s[64 * 128];          // 32KB
    __shared__ float ms[SEG_PER_CTA][64];
    __shared__ float invs[SEG_PER_CTA];
    const int tid = threadIdx.x;
    const int s0  = blockIdx.x * SEG_PER_CTA;

    for (int i = tid; i < 64 * 128 / 4; i += 128)
        reinterpret_cast<float4*>(w3s)[i] = reinterpret_cast<const float4*>(W3)[i];
    for (int i = tid; i < SEG_PER_CTA * 64; i += 128)
        ms[i >> 6][i & 63] = g_acc[(size_t)s0 * 64 + i];
    if (tid < SEG_PER_CTA) {
        const float c = g_cnt[s0 + tid];
        invs[tid] = (c > 0.0f) ? (1.0f / c) : 0.0f;
    }
    __syncthreads();

    const float b3v = b3[tid];
    #pragma unroll
    for (int ss = 0; ss < SEG_PER_CTA; ss++) {
        if (s0 + ss >= S) break;
        const float inv = invs[ss];
        float res = 0.0f;
        if (inv > 0.0f) {
            float d = 0.0f;
            #pragma unroll 8
            for (int j = 0; j < 64; j++)
                d = fmaf(ms[ss][j] * inv, w3s[j * 128 + tid], d);
            res = d + b3v;
        }
        out[(size_t)(s0 + ss) * 128 + tid] = res;   // empty segment -> exact zeros
    }
}

extern "C" void kernel_launch(void* const* d_in, const int* in_sizes, int n_in,
                              void* d_out, int out_size) {
    // metadata order: f_all, seg_ids, num_segments, W1, b1, W2, b2, W3, b3
    const float* f_all   = (const float*)d_in[0];
    const int*   seg_ids = (const int*)  d_in[1];
    const float* W1      = (const float*)d_in[3];
    const float* b1      = (const float*)d_in[4];
    const float* W2      = (const float*)d_in[5];
    const float* b2      = (const float*)d_in[6];
    const float* W3      = (const float*)d_in[7];
    const float* b3      = (const float*)d_in[8];
    float* out = (float*)d_out;

    const int N = in_sizes[1];
    const int S = out_size / 128;

    cudaFuncSetAttribute(mlp_accum_kernel,
                         cudaFuncAttributeMaxDynamicSharedMemorySize, SMEM_A);

    const int zthreads = S * 16 + S / 4;
    zero_kernel<<<(zthreads + 255) / 256, 256>>>(S);
    mlp_accum_kernel<<<GRID_A, TPB_A, SMEM_A>>>(f_all, seg_ids, N, W1, b1, W2, b2);
    seg_out_kernel<<<(S + SEG_PER_CTA - 1) / SEG_PER_CTA, 128>>>(W3, b3, out, S);
}

// round 13
// speedup vs baseline: 1.4904x; 1.4904x over previous
#include <cuda_runtime.h>
#include <cstdint>

// EmbedSocialFeatures: 3-layer MLP (64->32->64->128, ReLU x2) + segment mean.
// R12: fix R11 regression — persistent-grid wave quantization. Grid is now
// 2 x multiProcessorCount queried at launch (runtime attribute, capture-safe),
// never a hardcoded SM-count guess. Keeps R11's layer2 fp16 m16n8k16 and the
// W3-smem-cached seg_out (8 segs/CTA).

#define TPB_A  256
#define S_TILE 68      // f32 words per tile row (conflict-free staging + frag reads)
#define ROW_B  272     // bytes per tile row

// ---- smem layout (bytes), kernel A ----
#define TU0_OFF  0          // 34816: tile buffer 0 (128 x 68 f32)
#define TU1_OFF  34816      // 34816: tile buffer 1
#define SEG0_OFF 69632      // 512
#define SEG1_OFF 70144      // 512
#define W1F_OFF  70656      // 8192: 32 tf32 B-frags x 256B
#define W2F_OFF  78848      // 4096: 16 fp16 B-frags x 256B
#define B1S_OFF  87040      // 128
#define B2S_OFF  87168      // 256
#define SMEM_A   87424      // 2 CTAs/SM

#define MAXSEG 8192
__device__ float g_acc[MAXSEG * 64];
__device__ float g_cnt[MAXSEG];

static __device__ __forceinline__ uint32_t rna_tf32(float x) {
    uint32_t r;
    asm("cvt.rna.tf32.f32 %0, %1;" : "=r"(r) : "f"(x));
    return r;
}
// pack {lo, hi} f32 -> f16x2 (cvt d,a,b: hi=cvt(a), lo=cvt(b))
static __device__ __forceinline__ uint32_t pack_h2(float lo, float hi) {
    uint32_t r;
    asm("cvt.rn.f16x2.f32 %0, %1, %2;" : "=r"(r) : "f"(hi), "f"(lo));
    return r;
}
static __device__ __forceinline__ uint32_t smem_u32(const void* p) {
    uint32_t a;
    asm("{ .reg .u64 t; cvta.to.shared.u64 t, %1; cvt.u32.u64 %0, t; }" : "=r"(a) : "l"(p));
    return a;
}
static __device__ __forceinline__ void mma8(float d[4],
                                            uint32_t a0, uint32_t a1, uint32_t a2, uint32_t a3,
                                            uint32_t b0, uint32_t b1) {
    asm volatile(
        "mma.sync.aligned.m16n8k8.row.col.f32.tf32.tf32.f32 "
        "{%0,%1,%2,%3}, {%4,%5,%6,%7}, {%8,%9}, {%0,%1,%2,%3};"
        : "+f"(d[0]), "+f"(d[1]), "+f"(d[2]), "+f"(d[3])
        : "r"(a0), "r"(a1), "r"(a2), "r"(a3), "r"(b0), "r"(b1));
}
static __device__ __forceinline__ void mma16(float d[4],
                                             uint32_t a0, uint32_t a1, uint32_t a2, uint32_t a3,
                                             uint32_t b0, uint32_t b1) {
    asm volatile(
        "mma.sync.aligned.m16n8k16.row.col.f32.f16.f16.f32 "
        "{%0,%1,%2,%3}, {%4,%5,%6,%7}, {%8,%9}, {%0,%1,%2,%3};"
        : "+f"(d[0]), "+f"(d[1]), "+f"(d[2]), "+f"(d[3])
        : "r"(a0), "r"(a1), "r"(a2), "r"(a3), "r"(b0), "r"(b1));
}
#define CP_ASYNC16(dst, src) \
    asm volatile("cp.async.cg.shared.global [%0], [%1], 16;" :: "r"(dst), "l"(src) : "memory")
#define CP_COMMIT()  asm volatile("cp.async.commit_group;" ::: "memory")
#define CP_WAIT1()   asm volatile("cp.async.wait_group 1;" ::: "memory")

// ---------------- kernel 0: zero scratch (vectorized) ----------------
__global__ void zero_kernel(int S) {
    const int i = blockIdx.x * blockDim.x + threadIdx.x;
    const float4 z = make_float4(0.f, 0.f, 0.f, 0.f);
    if (i < S * 16) reinterpret_cast<float4*>(g_acc)[i] = z;
    const int j = i - S * 16;
    if (j >= 0 && j < S / 4) reinterpret_cast<float4*>(g_cnt)[j] = z;
}

// ---------------- kernel A: persistent tile GEMM + segmented accumulate ----------------
extern __shared__ char smemA[];

static __device__ __forceinline__ void issue_tile(
    const float* __restrict__ f_all, const int* __restrict__ seg_ids, int Nrows,
    int t, int tid, uint32_t sb_tu, float* tuf, int* segs)
{
    const int base = t * 128;
    const int nrows = min(128, Nrows - base);
    const char* src = (const char*)f_all + (size_t)base * 256;
    if (nrows == 128) {
        #pragma unroll
        for (int j = 0; j < 8; j++) {
            const int i = tid + j * TPB_A;
            const int r = i >> 4, q = i & 15;
            CP_ASYNC16(sb_tu + (uint32_t)(r * ROW_B + q * 16), src + (size_t)i * 16);
        }
        if (tid < 32)
            CP_ASYNC16(smem_u32(segs) + (uint32_t)(tid * 16),
                       (const char*)(seg_ids + base) + tid * 16);
    } else {
        for (int i = tid; i < nrows * 16; i += TPB_A) {
            const int r = i >> 4, q = i & 15;
            CP_ASYNC16(sb_tu + (uint32_t)(r * ROW_B + q * 16), src + (size_t)i * 16);
        }
        for (int i = nrows * 16 + tid; i < 2048; i += TPB_A) {
            const int r = i >> 4, q = i & 15;
            *(float4*)(&tuf[r * S_TILE + q * 4]) = make_float4(0.f, 0.f, 0.f, 0.f);
        }
        for (int r = tid; r < 128; r += TPB_A)
            segs[r] = __ldg(&seg_ids[base + min(r, nrows - 1)]);
    }
}

__global__ __launch_bounds__(TPB_A, 2)
void mlp_accum_kernel(const float* __restrict__ f_all,
                      const int*   __restrict__ seg_ids, int Nrows,
                      const float* __restrict__ W1, const float* __restrict__ b1,
                      const float* __restrict__ W2, const float* __restrict__ b2)
{
    const int tid   = threadIdx.x;
    const int lane  = tid & 31;
    const int wbase = (tid >> 5) * 16;     // warp's 16 rows in tile
    const int g     = lane >> 2;
    const int tig   = lane & 3;

    float* tuf0 = (float*)(smemA + TU0_OFF);
    float* tuf1 = (float*)(smemA + TU1_OFF);
    int*   seg0 = (int*)(smemA + SEG0_OFF);
    int*   seg1 = (int*)(smemA + SEG1_OFF);
    float* b1s  = (float*)(smemA + B1S_OFF);
    float* b2s  = (float*)(smemA + B2S_OFF);
    const uint32_t sb_tu0 = smem_u32(tuf0);
    const uint32_t sb_tu1 = smem_u32(tuf1);

    const int T      = (Nrows + 127) >> 7;
    const int stride = gridDim.x;
    const int t0     = blockIdx.x;

    if (t0 < T) issue_tile(f_all, seg_ids, Nrows, t0, tid, sb_tu0, tuf0, seg0);
    CP_COMMIT();

    // ---- W1 tf32 fragments (m16n8k8): frag f=k*4+n ----
    for (int idx = tid; idx < 1024; idx += TPB_A) {
        const int f = idx >> 5, l = idx & 31;
        const int k = f >> 2, n = f & 3, gg = l >> 2, t = l & 3;
        uint2 v;
        v.x = rna_tf32(__ldg(&W1[(8 * k + t) * 32 + 8 * n + gg]));
        v.y = rna_tf32(__ldg(&W1[(8 * k + t + 4) * 32 + 8 * n + gg]));
        *(uint2*)(smemA + W1F_OFF + f * 256 + l * 8) = v;
    }
    // ---- W2 fp16 fragments (m16n8k16): frag f = ks*8 + nb, col = 8nb+g ----
    for (int idx = tid; idx < 512; idx += TPB_A) {
        const int f = idx >> 5, l = idx & 31;
        const int ks = f >> 3, nb2 = f & 7, gg = l >> 2, t = l & 3;
        const int col = 8 * nb2 + gg;
        const int k0 = 16 * ks + 2 * t;
        uint2 v;
        v.x = pack_h2(__ldg(&W2[k0 * 64 + col]),       __ldg(&W2[(k0 + 1) * 64 + col]));
        v.y = pack_h2(__ldg(&W2[(k0 + 8) * 64 + col]), __ldg(&W2[(k0 + 9) * 64 + col]));
        *(uint2*)(smemA + W2F_OFF + f * 256 + l * 8) = v;
    }
    if (tid < 32) b1s[tid] = b1[tid];
    if (tid < 64) b2s[tid] = b2[tid];
    __syncthreads();

    float b1v0[4], b1v1[4];
    #pragma unroll
    for (int n = 0; n < 4; n++) {
        b1v0[n] = b1s[8 * n + 2 * tig];
        b1v1[n] = b1s[8 * n + 2 * tig + 1];
    }

    int buf = 0;
    for (int t = t0; t < T; t += stride) {
        const int nt = t + stride;
        if (nt < T)
            issue_tile(f_all, seg_ids, Nrows, nt, tid,
                       buf ? sb_tu0 : sb_tu1, buf ? tuf0 : tuf1, buf ? seg0 : seg1);
        CP_COMMIT();
        CP_WAIT1();
        __syncthreads();

        float*    tuf    = buf ? tuf1 : tuf0;
        uint32_t* tu     = (uint32_t*)tuf;
        int*      segs   = buf ? seg1 : seg0;
        const int nrows  = min(128, Nrows - t * 128);
        const int r0     = wbase + g;

        // ---- layer 1: tf32 m16n8k8, D1[16x32] ----
        float d1[4][4];
        #pragma unroll
        for (int n = 0; n < 4; n++)
            #pragma unroll
            for (int c = 0; c < 4; c++) d1[n][c] = 0.0f;
        #pragma unroll
        for (int k = 0; k < 8; k++) {
            const uint32_t a0 = rna_tf32(tuf[r0 * S_TILE + 8 * k + tig]);
            const uint32_t a1 = rna_tf32(tuf[(r0 + 8) * S_TILE + 8 * k + tig]);
            const uint32_t a2 = rna_tf32(tuf[r0 * S_TILE + 8 * k + tig + 4]);
            const uint32_t a3 = rna_tf32(tuf[(r0 + 8) * S_TILE + 8 * k + tig + 4]);
            #pragma unroll
            for (int n = 0; n < 4; n++) {
                const uint2 bf = *(const uint2*)(smemA + W1F_OFF + (k * 4 + n) * 256 + lane * 8);
                mma8(d1[n], a0, a1, a2, a3, bf.x, bf.y);
            }
        }

        // ---- epilogue 1: h1 = f16x2(relu(d1+b1)) at pair index p=4n+tig ----
        #pragma unroll
        for (int n = 0; n < 4; n++) {
            const float v00 = fmaxf(d1[n][0] + b1v0[n], 0.0f);
            const float v01 = fmaxf(d1[n][1] + b1v1[n], 0.0f);
            const float v10 = fmaxf(d1[n][2] + b1v0[n], 0.0f);
            const float v11 = fmaxf(d1[n][3] + b1v1[n], 0.0f);
            tu[r0 * S_TILE + 4 * n + tig]       = pack_h2(v00, v01);
            tu[(r0 + 8) * S_TILE + 4 * n + tig] = pack_h2(v10, v11);
        }
        __syncwarp();

        // ---- layer 2: fp16 m16n8k16, D2[16x64], K=32 in 2 k-steps ----
        float d2[8][4];
        #pragma unroll
        for (int q = 0; q < 8; q++)
            #pragma unroll
            for (int c = 0; c < 4; c++) d2[q][c] = 0.0f;
        #pragma unroll
        for (int ks = 0; ks < 2; ks++) {
            const uint32_t a0 = tu[r0 * S_TILE + 8 * ks + tig];
            const uint32_t a1 = tu[(r0 + 8) * S_TILE + 8 * ks + tig];
            const uint32_t a2 = tu[r0 * S_TILE + 8 * ks + tig + 4];
            const uint32_t a3 = tu[(r0 + 8) * S_TILE + 8 * ks + tig + 4];
            #pragma unroll
            for (int q = 0; q < 8; q++) {
                const uint2 bf = *(const uint2*)(smemA + W2F_OFF + (ks * 8 + q) * 256 + lane * 8);
                mma16(d2[q], a0, a1, a2, a3, bf.x, bf.y);
            }
        }

        // ---- epilogue 2: masked relu(h2) f32 stash over own rows ----
        {
            const float m0 = (r0 < nrows) ? 1.0f : 0.0f;
            const float m1 = (r0 + 8 < nrows) ? 1.0f : 0.0f;
            #pragma unroll
            for (int q = 0; q < 8; q++) {
                const int c = 8 * q + 2 * tig;
                const float bv0 = b2s[c], bv1 = b2s[c + 1];
                float2 v0, v1;
                v0.x = m0 * fmaxf(d2[q][0] + bv0, 0.0f);
                v0.y = m0 * fmaxf(d2[q][1] + bv1, 0.0f);
                v1.x = m1 * fmaxf(d2[q][2] + bv0, 0.0f);
                v1.y = m1 * fmaxf(d2[q][3] + bv1, 0.0f);
                *(float2*)(&tuf[r0 * S_TILE + c]) = v0;
                *(float2*)(&tuf[(r0 + 8) * S_TILE + c]) = v1;
            }
        }
        __syncthreads();

        // ---- segmented run-scan: quarter q rows [32q,32q+32), column c ----
        {
            const int q = tid >> 6, c = tid & 63;
            const int rq = q * 32;
            int cur = segs[rq];
            float run = 0.0f, crun = 0.0f;
            #pragma unroll 4
            for (int r = rq; r < rq + 32; r++) {
                const int sg = segs[r];
                if (sg != cur) {
                    atomicAdd(&g_acc[cur * 64 + c], run);
                    if (c == 0) atomicAdd(&g_cnt[cur], crun);
                    run = 0.0f; crun = 0.0f; cur = sg;
                }
                run += tuf[r * S_TILE + c];
                if (r < nrows) crun += 1.0f;
            }
            atomicAdd(&g_acc[cur * 64 + c], run);
            if (c == 0) atomicAdd(&g_cnt[cur], crun);
        }
        __syncthreads();
        buf ^= 1;
    }
}

// ---------------- kernel B: per-segment mean @ W3 + b3 (W3 smem-cached) ----------------
#define SEG_PER_CTA 8
__global__ __launch_bounds__(128)
void seg_out_kernel(const float* __restrict__ W3, const float* __restrict__ b3,
                    float* __restrict__ out, int S)
{
    __shared__ float w3s[64 * 128];          // 32KB
    __shared__ float ms[SEG_PER_CTA][64];
    __shared__ float invs[SEG_PER_CTA];
    const int tid = threadIdx.x;
    const int s0  = blockIdx.x * SEG_PER_CTA;

    for (int i = tid; i < 64 * 128 / 4; i += 128)
        reinterpret_cast<float4*>(w3s)[i] = reinterpret_cast<const float4*>(W3)[i];
    for (int i = tid; i < SEG_PER_CTA * 64; i += 128)
        ms[i >> 6][i & 63] = g_acc[(size_t)s0 * 64 + i];
    if (tid < SEG_PER_CTA) {
        const float c = g_cnt[s0 + tid];
        invs[tid] = (c > 0.0f) ? (1.0f / c) : 0.0f;
    }
    __syncthreads();

    const float b3v = b3[tid];
    #pragma unroll
    for (int ss = 0; ss < SEG_PER_CTA; ss++) {
        if (s0 + ss >= S) break;
        const float inv = invs[ss];
        float res = 0.0f;
        if (inv > 0.0f) {
            float d = 0.0f;
            #pragma unroll 8
            for (int j = 0; j < 64; j++)
                d = fmaf(ms[ss][j] * inv, w3s[j * 128 + tid], d);
            res = d + b3v;
        }
        out[(size_t)(s0 + ss) * 128 + tid] = res;   // empty segment -> exact zeros
    }
}

extern "C" void kernel_launch(void* const* d_in, const int* in_sizes, int n_in,
                              void* d_out, int out_size) {
    // metadata order: f_all, seg_ids, num_segments, W1, b1, W2, b2, W3, b3
    const float* f_all   = (const float*)d_in[0];
    const int*   seg_ids = (const int*)  d_in[1];
    const float* W1      = (const float*)d_in[3];
    const float* b1      = (const float*)d_in[4];
    const float* W2      = (const float*)d_in[5];
    const float* b2      = (const float*)d_in[6];
    const float* W3      = (const float*)d_in[7];
    const float* b3      = (const float*)d_in[8];
    float* out = (float*)d_out;

    const int N = in_sizes[1];
    const int S = out_size / 128;

    // persistent grid = 2 CTAs per SM, queried from the device (no wave quantization)
    int dev = 0, sms = 148;
    cudaGetDevice(&dev);
    cudaDeviceGetAttribute(&sms, cudaDevAttrMultiProcessorCount, dev);
    const int grid_a = 2 * sms;

    cudaFuncSetAttribute(mlp_accum_kernel,
                         cudaFuncAttributeMaxDynamicSharedMemorySize, SMEM_A);

    const int zthreads = S * 16 + S / 4;
    zero_kernel<<<(zthreads + 255) / 256, 256>>>(S);
    mlp_accum_kernel<<<grid_a, TPB_A, SMEM_A>>>(f_all, seg_ids, N, W1, b1, W2, b2);
    seg_out_kernel<<<(S + SEG_PER_CTA - 1) / SEG_PER_CTA, 128>>>(W3, b3, out, S);
}

// round 16
// speedup vs baseline: 1.5079x; 1.0118x over previous
#include <cuda_runtime.h>
#include <cstdint>

// EmbedSocialFeatures: 3-layer MLP (64->32->64->128, ReLU x2) + segment mean.
// R14: A-operands via ldmatrix.m8n8.x4 (1 instr per 4-reg fragment, replaces
// 4 scalar LDS + 4 cvt) for both layers; raw-f32-as-tf32 (HW truncation) kills
// the per-read cvt.rna; d1 bias-init. Grid = 2 x queried SM count (R12 fix).
// Layer1 tf32 m16n8k8, layer2 fp16 m16n8k16, W3-smem seg_out, cp.async x2.

#define TPB_A  256
#define S_TILE 68      // f32 words per tile row (staging + ldmatrix conflict-free)
#define ROW_B  272     // bytes per tile row

// ---- smem layout (bytes), kernel A ----
#define TU0_OFF  0          // 34816: tile buffer 0 (128 x 68 f32)
#define TU1_OFF  34816      // 34816: tile buffer 1
#define SEG0_OFF 69632      // 512
#define SEG1_OFF 70144      // 512
#define W1F_OFF  70656      // 8192: 32 tf32 B-frags x 256B
#define W2F_OFF  78848      // 4096: 16 fp16 B-frags x 256B
#define B1S_OFF  87040      // 128
#define B2S_OFF  87168      // 256
#define SMEM_A   87424      // 2 CTAs/SM

#define MAXSEG 8192
__device__ float g_acc[MAXSEG * 64];
__device__ float g_cnt[MAXSEG];

static __device__ __forceinline__ uint32_t rna_tf32(float x) {
    uint32_t r;
    asm("cvt.rna.tf32.f32 %0, %1;" : "=r"(r) : "f"(x));
    return r;
}
// pack {lo, hi} f32 -> f16x2 (cvt d,a,b: hi=cvt(a), lo=cvt(b))
static __device__ __forceinline__ uint32_t pack_h2(float lo, float hi) {
    uint32_t r;
    asm("cvt.rn.f16x2.f32 %0, %1, %2;" : "=r"(r) : "f"(hi), "f"(lo));
    return r;
}
static __device__ __forceinline__ uint32_t smem_u32(const void* p) {
    uint32_t a;
    asm("{ .reg .u64 t; cvta.to.shared.u64 t, %1; cvt.u32.u64 %0, t; }" : "=r"(a) : "l"(p));
    return a;
}
static __device__ __forceinline__ void ldmx4(uint32_t& r0, uint32_t& r1,
                                             uint32_t& r2, uint32_t& r3, uint32_t addr) {
    asm volatile("ldmatrix.sync.aligned.m8n8.x4.shared.b16 {%0,%1,%2,%3}, [%4];"
                 : "=r"(r0), "=r"(r1), "=r"(r2), "=r"(r3) : "r"(addr));
}
static __device__ __forceinline__ void mma8(float d[4],
                                            uint32_t a0, uint32_t a1, uint32_t a2, uint32_t a3,
                                            uint32_t b0, uint32_t b1) {
    asm volatile(
        "mma.sync.aligned.m16n8k8.row.col.f32.tf32.tf32.f32 "
        "{%0,%1,%2,%3}, {%4,%5,%6,%7}, {%8,%9}, {%0,%1,%2,%3};"
        : "+f"(d[0]), "+f"(d[1]), "+f"(d[2]), "+f"(d[3])
        : "r"(a0), "r"(a1), "r"(a2), "r"(a3), "r"(b0), "r"(b1));
}
static __device__ __forceinline__ void mma16(float d[4],
                                             uint32_t a0, uint32_t a1, uint32_t a2, uint32_t a3,
                                             uint32_t b0, uint32_t b1) {
    asm volatile(
        "mma.sync.aligned.m16n8k16.row.col.f32.f16.f16.f32 "
        "{%0,%1,%2,%3}, {%4,%5,%6,%7}, {%8,%9}, {%0,%1,%2,%3};"
        : "+f"(d[0]), "+f"(d[1]), "+f"(d[2]), "+f"(d[3])
        : "r"(a0), "r"(a1), "r"(a2), "r"(a3), "r"(b0), "r"(b1));
}
#define CP_ASYNC16(dst, src) \
    asm volatile("cp.async.cg.shared.global [%0], [%1], 16;" :: "r"(dst), "l"(src) : "memory")
#define CP_COMMIT()  asm volatile("cp.async.commit_group;" ::: "memory")
#define CP_WAIT1()   asm volatile("cp.async.wait_group 1;" ::: "memory")

// ---------------- kernel 0: zero scratch (vectorized) ----------------
__global__ void zero_kernel(int S) {
    const int i = blockIdx.x * blockDim.x + threadIdx.x;
    const float4 z = make_float4(0.f, 0.f, 0.f, 0.f);
    if (i < S * 16) reinterpret_cast<float4*>(g_acc)[i] = z;
    const int j = i - S * 16;
    if (j >= 0 && j < S / 4) reinterpret_cast<float4*>(g_cnt)[j] = z;
}

// ---------------- kernel A: persistent tile GEMM + segmented accumulate ----------------
extern __shared__ char smemA[];

static __device__ __forceinline__ void issue_tile(
    const float* __restrict__ f_all, const int* __restrict__ seg_ids, int Nrows,
    int t, int tid, uint32_t sb_tu, float* tuf, int* segs)
{
    const int base = t * 128;
    const int nrows = min(128, Nrows - base);
    const char* src = (const char*)f_all + (size_t)base * 256;
    if (nrows == 128) {
        #pragma unroll
        for (int j = 0; j < 8; j++) {
            const int i = tid + j * TPB_A;
            const int r = i >> 4, q = i & 15;
            CP_ASYNC16(sb_tu + (uint32_t)(r * ROW_B + q * 16), src + (size_t)i * 16);
        }
        if (tid < 32)
            CP_ASYNC16(smem_u32(segs) + (uint32_t)(tid * 16),
                       (const char*)(seg_ids + base) + tid * 16);
    } else {
        for (int i = tid; i < nrows * 16; i += TPB_A) {
            const int r = i >> 4, q = i & 15;
            CP_ASYNC16(sb_tu + (uint32_t)(r * ROW_B + q * 16), src + (size_t)i * 16);
        }
        for (int i = nrows * 16 + tid; i < 2048; i += TPB_A) {
            const int r = i >> 4, q = i & 15;
            *(float4*)(&tuf[r * S_TILE + q * 4]) = make_float4(0.f, 0.f, 0.f, 0.f);
        }
        for (int r = tid; r < 128; r += TPB_A)
            segs[r] = __ldg(&seg_ids[base + min(r, nrows - 1)]);
    }
}

__global__ __launch_bounds__(TPB_A, 2)
void mlp_accum_kernel(const float* __restrict__ f_all,
                      const int*   __restrict__ seg_ids, int Nrows,
                      const float* __restrict__ W1, const float* __restrict__ b1,
                      const float* __restrict__ W2, const float* __restrict__ b2)
{
    const int tid   = threadIdx.x;
    const int lane  = tid & 31;
    const int wbase = (tid >> 5) * 16;     // warp's 16 rows in tile
    const int g     = lane >> 2;
    const int tig   = lane & 3;

    float* tuf0 = (float*)(smemA + TU0_OFF);
    float* tuf1 = (float*)(smemA + TU1_OFF);
    int*   seg0 = (int*)(smemA + SEG0_OFF);
    int*   seg1 = (int*)(smemA + SEG1_OFF);
    float* b1s  = (float*)(smemA + B1S_OFF);
    float* b2s  = (float*)(smemA + B2S_OFF);
    const uint32_t sb_tu0 = smem_u32(tuf0);
    const uint32_t sb_tu1 = smem_u32(tuf1);

    // ldmatrix per-lane base: blocks {rows wbase..+7, +8..+15} x {col +0B, +16B}
    const int lrow = wbase + (lane & 7) + ((lane >> 3) & 1) * 8;
    const uint32_t lcoff = (uint32_t)((lane >> 4) * 16);
    const uint32_t lmb0 = sb_tu0 + (uint32_t)lrow * ROW_B + lcoff;
    const uint32_t lmb1 = sb_tu1 + (uint32_t)lrow * ROW_B + lcoff;

    const int T      = (Nrows + 127) >> 7;
    const int stride = gridDim.x;
    const int t0     = blockIdx.x;

    if (t0 < T) issue_tile(f_all, seg_ids, Nrows, t0, tid, sb_tu0, tuf0, seg0);
    CP_COMMIT();

    // ---- W1 tf32 fragments (m16n8k8): frag f=k*4+n ----
    for (int idx = tid; idx < 1024; idx += TPB_A) {
        const int f = idx >> 5, l = idx & 31;
        const int k = f >> 2, n = f & 3, gg = l >> 2, t = l & 3;
        uint2 v;
        v.x = rna_tf32(__ldg(&W1[(8 * k + t) * 32 + 8 * n + gg]));
        v.y = rna_tf32(__ldg(&W1[(8 * k + t + 4) * 32 + 8 * n + gg]));
        *(uint2*)(smemA + W1F_OFF + f * 256 + l * 8) = v;
    }
    // ---- W2 fp16 fragments (m16n8k16): frag f = ks*8 + nb, col = 8nb+g ----
    for (int idx = tid; idx < 512; idx += TPB_A) {
        const int f = idx >> 5, l = idx & 31;
        const int ks = f >> 3, nb2 = f & 7, gg = l >> 2, t = l & 3;
        const int col = 8 * nb2 + gg;
        const int k0 = 16 * ks + 2 * t;
        uint2 v;
        v.x = pack_h2(__ldg(&W2[k0 * 64 + col]),       __ldg(&W2[(k0 + 1) * 64 + col]));
        v.y = pack_h2(__ldg(&W2[(k0 + 8) * 64 + col]), __ldg(&W2[(k0 + 9) * 64 + col]));
        *(uint2*)(smemA + W2F_OFF + f * 256 + l * 8) = v;
    }
    if (tid < 32) b1s[tid] = b1[tid];
    if (tid < 64) b2s[tid] = b2[tid];
    __syncthreads();

    float b1v0[4], b1v1[4];
    #pragma unroll
    for (int n = 0; n < 4; n++) {
        b1v0[n] = b1s[8 * n + 2 * tig];
        b1v1[n] = b1s[8 * n + 2 * tig + 1];
    }

    int buf = 0;
    for (int t = t0; t < T; t += stride) {
        const int nt = t + stride;
        if (nt < T)
            issue_tile(f_all, seg_ids, Nrows, nt, tid,
                       buf ? sb_tu0 : sb_tu1, buf ? tuf0 : tuf1, buf ? seg0 : seg1);
        CP_COMMIT();
        CP_WAIT1();
        __syncthreads();

        float*    tuf    = buf ? tuf1 : tuf0;
        uint32_t* tu     = (uint32_t*)tuf;
        int*      segs   = buf ? seg1 : seg0;
        const uint32_t lmb = buf ? lmb1 : lmb0;
        const int nrows  = min(128, Nrows - t * 128);
        const int r0     = wbase + g;

        // ---- layer 1: tf32 m16n8k8, D1[16x32], bias pre-init ----
        float d1[4][4];
        #pragma unroll
        for (int n = 0; n < 4; n++) {
            d1[n][0] = b1v0[n]; d1[n][1] = b1v1[n];
            d1[n][2] = b1v0[n]; d1[n][3] = b1v1[n];
        }
        #pragma unroll
        for (int k = 0; k < 8; k++) {
            uint32_t a0, a1, a2, a3;
            ldmx4(a0, a1, a2, a3, lmb + 32u * k);   // raw f32 bits -> tf32 (HW truncation)
            #pragma unroll
            for (int n = 0; n < 4; n++) {
                const uint2 bf = *(const uint2*)(smemA + W1F_OFF + (k * 4 + n) * 256 + lane * 8);
                mma8(d1[n], a0, a1, a2, a3, bf.x, bf.y);
            }
        }

        // ---- epilogue 1: h1 = f16x2(relu(d1)) at pair index p=4n+tig ----
        #pragma unroll
        for (int n = 0; n < 4; n++) {
            tu[r0 * S_TILE + 4 * n + tig] =
                pack_h2(fmaxf(d1[n][0], 0.0f), fmaxf(d1[n][1], 0.0f));
            tu[(r0 + 8) * S_TILE + 4 * n + tig] =
                pack_h2(fmaxf(d1[n][2], 0.0f), fmaxf(d1[n][3], 0.0f));
        }
        __syncwarp();

        // ---- layer 2: fp16 m16n8k16, D2[16x64], K=32 in 2 k-steps ----
        float d2[8][4];
        #pragma unroll
        for (int q = 0; q < 8; q++)
            #pragma unroll
            for (int c = 0; c < 4; c++) d2[q][c] = 0.0f;
        #pragma unroll
        for (int ks = 0; ks < 2; ks++) {
            uint32_t a0, a1, a2, a3;
            ldmx4(a0, a1, a2, a3, lmb + 32u * ks);  // h1 f16x2, ldmatrix-native
            #pragma unroll
            for (int q = 0; q < 8; q++) {
                const uint2 bf = *(const uint2*)(smemA + W2F_OFF + (ks * 8 + q) * 256 + lane * 8);
                mma16(d2[q], a0, a1, a2, a3, bf.x, bf.y);
            }
        }

        // ---- epilogue 2: masked relu(h2+b2) f32 stash over own rows ----
        {
            const float m0 = (r0 < nrows) ? 1.0f : 0.0f;
            const float m1 = (r0 + 8 < nrows) ? 1.0f : 0.0f;
            #pragma unroll
            for (int q = 0; q < 8; q++) {
                const int c = 8 * q + 2 * tig;
                const float bv0 = b2s[c], bv1 = b2s[c + 1];
                float2 v0, v1;
                v0.x = m0 * fmaxf(d2[q][0] + bv0, 0.0f);
                v0.y = m0 * fmaxf(d2[q][1] + bv1, 0.0f);
                v1.x = m1 * fmaxf(d2[q][2] + bv0, 0.0f);
                v1.y = m1 * fmaxf(d2[q][3] + bv1, 0.0f);
                *(float2*)(&tuf[r0 * S_TILE + c]) = v0;
                *(float2*)(&tuf[(r0 + 8) * S_TILE + c]) = v1;
            }
        }
        __syncthreads();

        // ---- segmented run-scan: quarter q rows [32q,32q+32), column c ----
        {
            const int q = tid >> 6, c = tid & 63;
            const int rq = q * 32;
            int cur = segs[rq];
            float run = 0.0f, crun = 0.0f;
            #pragma unroll 4
            for (int r = rq; r < rq + 32; r++) {
                const int sg = segs[r];
                if (sg != cur) {
                    atomicAdd(&g_acc[cur * 64 + c], run);
                    if (c == 0) atomicAdd(&g_cnt[cur], crun);
                    run = 0.0f; crun = 0.0f; cur = sg;
                }
                run += tuf[r * S_TILE + c];
                if (r < nrows) crun += 1.0f;
            }
            atomicAdd(&g_acc[cur * 64 + c], run);
            if (c == 0) atomicAdd(&g_cnt[cur], crun);
        }
        __syncthreads();
        buf ^= 1;
    }
}

// ---------------- kernel B: per-segment mean @ W3 + b3 (W3 smem-cached) ----------------
#define SEG_PER_CTA 8
__global__ __launch_bounds__(128)
void seg_out_kernel(const float* __restrict__ W3, const float* __restrict__ b3,
                    float* __restrict__ out, int S)
{
    __shared__ float w3s[64 * 128];          // 32KB
    __shared__ float ms[SEG_PER_CTA][64];
    __shared__ float invs[SEG_PER_CTA];
    const int tid = threadIdx.x;
    const int s0  = blockIdx.x * SEG_PER_CTA;

    for (int i = tid; i < 64 * 128 / 4; i += 128)
        reinterpret_cast<float4*>(w3s)[i] = reinterpret_cast<const float4*>(W3)[i];
    for (int i = tid; i < SEG_PER_CTA * 64; i += 128)
        ms[i >> 6][i & 63] = g_acc[(size_t)s0 * 64 + i];
    if (tid < SEG_PER_CTA) {
        const float c = g_cnt[s0 + tid];
        invs[tid] = (c > 0.0f) ? (1.0f / c) : 0.0f;
    }
    __syncthreads();

    const float b3v = b3[tid];
    #pragma unroll
    for (int ss = 0; ss < SEG_PER_CTA; ss++) {
        if (s0 + ss >= S) break;
        const float inv = invs[ss];
        float res = 0.0f;
        if (inv > 0.0f) {
            float d = 0.0f;
            #pragma unroll 8
            for (int j = 0; j < 64; j++)
                d = fmaf(ms[ss][j] * inv, w3s[j * 128 + tid], d);
            res = d + b3v;
        }
        out[(size_t)(s0 + ss) * 128 + tid] = res;   // empty segment -> exact zeros
    }
}

extern "C" void kernel_launch(void* const* d_in, const int* in_sizes, int n_in,
                              void* d_out, int out_size) {
    // metadata order: f_all, seg_ids, num_segments, W1, b1, W2, b2, W3, b3
    const float* f_all   = (const float*)d_in[0];
    const int*   seg_ids = (const int*)  d_in[1];
    const float* W1      = (const float*)d_in[3];
    const float* b1      = (const float*)d_in[4];
    const float* W2      = (const float*)d_in[5];
    const float* b2      = (const float*)d_in[6];
    const float* W3      = (const float*)d_in[7];
    const float* b3      = (const float*)d_in[8];
    float* out = (float*)d_out;

    const int N = in_sizes[1];
    const int S = out_size / 128;

    // persistent grid = 2 CTAs per SM, queried from the device (no wave quantization)
    int dev = 0, sms = 148;
    cudaGetDevice(&dev);
    cudaDeviceGetAttribute(&sms, cudaDevAttrMultiProcessorCount, dev);
    const int grid_a = 2 * sms;

    cudaFuncSetAttribute(mlp_accum_kernel,
                         cudaFuncAttributeMaxDynamicSharedMemorySize, SMEM_A);

    const int zthreads = S * 16 + S / 4;
    zero_kernel<<<(zthreads + 255) / 256, 256>>>(S);
    mlp_accum_kernel<<<grid_a, TPB_A, SMEM_A>>>(f_all, seg_ids, N, W1, b1, W2, b2);
    seg_out_kernel<<<(S + SEG_PER_CTA - 1) / SEG_PER_CTA, 128>>>(W3, b3, out, S);
}

// round 17
// speedup vs baseline: 1.6345x; 1.0840x over previous
#include <cuda_runtime.h>
#include <cstdint>

// EmbedSocialFeatures: 3-layer MLP (64->32->64->128, ReLU x2) + segment mean.
// R17: kill the per-tile smem stash + segmented run-scan (was ~45% of L1
// wavefronts + the longest serial chain). relu(h2) stays in registers; warp
// reduces its 16 rows per segment via shfl-xor + REDG straight to g_acc,
// boundary loop via __reduce_min_sync, counts via ballot. 3 syncthreads -> 2,
// reduction overlaps next tile's cp.async fill.

#define TPB_A  256
#define S_TILE 68      // f32 words per tile row (staging + ldmatrix conflict-free)
#define ROW_B  272     // bytes per tile row

// ---- smem layout (bytes), kernel A ----
#define TU0_OFF  0          // 34816: tile buffer 0 (128 x 68 f32)
#define TU1_OFF  34816      // 34816: tile buffer 1
#define SEG0_OFF 69632      // 512
#define SEG1_OFF 70144      // 512
#define W1F_OFF  70656      // 8192: 32 tf32 B-frags x 256B
#define W2F_OFF  78848      // 4096: 16 fp16 B-frags x 256B
#define B1S_OFF  87040      // 128
#define B2S_OFF  87168      // 256
#define SMEM_A   87424      // 2 CTAs/SM

#define MAXSEG 8192
__device__ float g_acc[MAXSEG * 64];
__device__ float g_cnt[MAXSEG];

static __device__ __forceinline__ uint32_t rna_tf32(float x) {
    uint32_t r;
    asm("cvt.rna.tf32.f32 %0, %1;" : "=r"(r) : "f"(x));
    return r;
}
// pack {lo, hi} f32 -> f16x2 (cvt d,a,b: hi=cvt(a), lo=cvt(b))
static __device__ __forceinline__ uint32_t pack_h2(float lo, float hi) {
    uint32_t r;
    asm("cvt.rn.f16x2.f32 %0, %1, %2;" : "=r"(r) : "f"(hi), "f"(lo));
    return r;
}
static __device__ __forceinline__ uint32_t smem_u32(const void* p) {
    uint32_t a;
    asm("{ .reg .u64 t; cvta.to.shared.u64 t, %1; cvt.u32.u64 %0, t; }" : "=r"(a) : "l"(p));
    return a;
}
static __device__ __forceinline__ void ldmx4(uint32_t& r0, uint32_t& r1,
                                             uint32_t& r2, uint32_t& r3, uint32_t addr) {
    asm volatile("ldmatrix.sync.aligned.m8n8.x4.shared.b16 {%0,%1,%2,%3}, [%4];"
                 : "=r"(r0), "=r"(r1), "=r"(r2), "=r"(r3) : "r"(addr));
}
static __device__ __forceinline__ void mma8(float d[4],
                                            uint32_t a0, uint32_t a1, uint32_t a2, uint32_t a3,
                                            uint32_t b0, uint32_t b1) {
    asm volatile(
        "mma.sync.aligned.m16n8k8.row.col.f32.tf32.tf32.f32 "
        "{%0,%1,%2,%3}, {%4,%5,%6,%7}, {%8,%9}, {%0,%1,%2,%3};"
        : "+f"(d[0]), "+f"(d[1]), "+f"(d[2]), "+f"(d[3])
        : "r"(a0), "r"(a1), "r"(a2), "r"(a3), "r"(b0), "r"(b1));
}
static __device__ __forceinline__ void mma16(float d[4],
                                             uint32_t a0, uint32_t a1, uint32_t a2, uint32_t a3,
                                             uint32_t b0, uint32_t b1) {
    asm volatile(
        "mma.sync.aligned.m16n8k16.row.col.f32.f16.f16.f32 "
        "{%0,%1,%2,%3}, {%4,%5,%6,%7}, {%8,%9}, {%0,%1,%2,%3};"
        : "+f"(d[0]), "+f"(d[1]), "+f"(d[2]), "+f"(d[3])
        : "r"(a0), "r"(a1), "r"(a2), "r"(a3), "r"(b0), "r"(b1));
}
#define CP_ASYNC16(dst, src) \
    asm volatile("cp.async.cg.shared.global [%0], [%1], 16;" :: "r"(dst), "l"(src) : "memory")
#define CP_COMMIT()  asm volatile("cp.async.commit_group;" ::: "memory")
#define CP_WAIT1()   asm volatile("cp.async.wait_group 1;" ::: "memory")

// ---------------- kernel 0: zero scratch (vectorized) ----------------
__global__ void zero_kernel(int S) {
    const int i = blockIdx.x * blockDim.x + threadIdx.x;
    const float4 z = make_float4(0.f, 0.f, 0.f, 0.f);
    if (i < S * 16) reinterpret_cast<float4*>(g_acc)[i] = z;
    const int j = i - S * 16;
    if (j >= 0 && j < S / 4) reinterpret_cast<float4*>(g_cnt)[j] = z;
}

// ---------------- kernel A: persistent tile GEMM + register-resident reduce ----------------
extern __shared__ char smemA[];

static __device__ __forceinline__ void issue_tile(
    const float* __restrict__ f_all, const int* __restrict__ seg_ids, int Nrows,
    int t, int tid, uint32_t sb_tu, float* tuf, int* segs)
{
    const int base = t * 128;
    const int nrows = min(128, Nrows - base);
    const char* src = (const char*)f_all + (size_t)base * 256;
    if (nrows == 128) {
        #pragma unroll
        for (int j = 0; j < 8; j++) {
            const int i = tid + j * TPB_A;
            const int r = i >> 4, q = i & 15;
            CP_ASYNC16(sb_tu + (uint32_t)(r * ROW_B + q * 16), src + (size_t)i * 16);
        }
        if (tid < 32)
            CP_ASYNC16(smem_u32(segs) + (uint32_t)(tid * 16),
                       (const char*)(seg_ids + base) + tid * 16);
    } else {
        for (int i = tid; i < nrows * 16; i += TPB_A) {
            const int r = i >> 4, q = i & 15;
            CP_ASYNC16(sb_tu + (uint32_t)(r * ROW_B + q * 16), src + (size_t)i * 16);
        }
        for (int i = nrows * 16 + tid; i < 2048; i += TPB_A) {
            const int r = i >> 4, q = i & 15;
            *(float4*)(&tuf[r * S_TILE + q * 4]) = make_float4(0.f, 0.f, 0.f, 0.f);
        }
        for (int r = tid; r < 128; r += TPB_A)
            segs[r] = __ldg(&seg_ids[base + min(r, nrows - 1)]);
    }
}

__global__ __launch_bounds__(TPB_A, 2)
void mlp_accum_kernel(const float* __restrict__ f_all,
                      const int*   __restrict__ seg_ids, int Nrows,
                      const float* __restrict__ W1, const float* __restrict__ b1,
                      const float* __restrict__ W2, const float* __restrict__ b2)
{
    const int tid   = threadIdx.x;
    const int lane  = tid & 31;
    const int wbase = (tid >> 5) * 16;     // warp's 16 rows in tile
    const int g     = lane >> 2;
    const int tig   = lane & 3;

    float* tuf0 = (float*)(smemA + TU0_OFF);
    float* tuf1 = (float*)(smemA + TU1_OFF);
    int*   seg0 = (int*)(smemA + SEG0_OFF);
    int*   seg1 = (int*)(smemA + SEG1_OFF);
    float* b1s  = (float*)(smemA + B1S_OFF);
    float* b2s  = (float*)(smemA + B2S_OFF);
    const uint32_t sb_tu0 = smem_u32(tuf0);
    const uint32_t sb_tu1 = smem_u32(tuf1);

    // ldmatrix per-lane base: blocks {rows wbase..+7, +8..+15} x {col +0B, +16B}
    const int lrow = wbase + (lane & 7) + ((lane >> 3) & 1) * 8;
    const uint32_t lcoff = (uint32_t)((lane >> 4) * 16);
    const uint32_t lmb0 = sb_tu0 + (uint32_t)lrow * ROW_B + lcoff;
    const uint32_t lmb1 = sb_tu1 + (uint32_t)lrow * ROW_B + lcoff;

    const int T      = (Nrows + 127) >> 7;
    const int stride = gridDim.x;
    const int t0     = blockIdx.x;

    if (t0 < T) issue_tile(f_all, seg_ids, Nrows, t0, tid, sb_tu0, tuf0, seg0);
    CP_COMMIT();

    // ---- W1 tf32 fragments (m16n8k8): frag f=k*4+n ----
    for (int idx = tid; idx < 1024; idx += TPB_A) {
        const int f = idx >> 5, l = idx & 31;
        const int k = f >> 2, n = f & 3, gg = l >> 2, t = l & 3;
        uint2 v;
        v.x = rna_tf32(__ldg(&W1[(8 * k + t) * 32 + 8 * n + gg]));
        v.y = rna_tf32(__ldg(&W1[(8 * k + t + 4) * 32 + 8 * n + gg]));
        *(uint2*)(smemA + W1F_OFF + f * 256 + l * 8) = v;
    }
    // ---- W2 fp16 fragments (m16n8k16): frag f = ks*8 + nb, col = 8nb+g ----
    for (int idx = tid; idx < 512; idx += TPB_A) {
        const int f = idx >> 5, l = idx & 31;
        const int ks = f >> 3, nb2 = f & 7, gg = l >> 2, t = l & 3;
        const int col = 8 * nb2 + gg;
        const int k0 = 16 * ks + 2 * t;
        uint2 v;
        v.x = pack_h2(__ldg(&W2[k0 * 64 + col]),       __ldg(&W2[(k0 + 1) * 64 + col]));
        v.y = pack_h2(__ldg(&W2[(k0 + 8) * 64 + col]), __ldg(&W2[(k0 + 9) * 64 + col]));
        *(uint2*)(smemA + W2F_OFF + f * 256 + l * 8) = v;
    }
    if (tid < 32) b1s[tid] = b1[tid];
    if (tid < 64) b2s[tid] = b2[tid];
    __syncthreads();

    float b1v0[4], b1v1[4];
    #pragma unroll
    for (int n = 0; n < 4; n++) {
        b1v0[n] = b1s[8 * n + 2 * tig];
        b1v1[n] = b1s[8 * n + 2 * tig + 1];
    }
    float b2v0[8], b2v1[8];
    #pragma unroll
    for (int q = 0; q < 8; q++) {
        b2v0[q] = b2s[8 * q + 2 * tig];
        b2v1[q] = b2s[8 * q + 2 * tig + 1];
    }

    int buf = 0;
    for (int t = t0; t < T; t += stride) {
        const int nt = t + stride;
        if (nt < T)
            issue_tile(f_all, seg_ids, Nrows, nt, tid,
                       buf ? sb_tu0 : sb_tu1, buf ? tuf0 : tuf1, buf ? seg0 : seg1);
        CP_COMMIT();
        CP_WAIT1();              // current tile's group complete (newest may pend)
        __syncthreads();         // visible to all warps

        uint32_t* tu   = (uint32_t*)(buf ? tuf1 : tuf0);
        int*      segs = buf ? seg1 : seg0;
        const uint32_t lmb = buf ? lmb1 : lmb0;
        const int nrows  = min(128, Nrows - t * 128);
        const int r0     = wbase + g;

        // segment ids of this thread's two rows (into regs before the tail barrier)
        const int segA = segs[r0];
        const int segB = segs[r0 + 8];

        // ---- layer 1: tf32 m16n8k8, D1[16x32], bias pre-init ----
        float d1[4][4];
        #pragma unroll
        for (int n = 0; n < 4; n++) {
            d1[n][0] = b1v0[n]; d1[n][1] = b1v1[n];
            d1[n][2] = b1v0[n]; d1[n][3] = b1v1[n];
        }
        #pragma unroll
        for (int k = 0; k < 8; k++) {
            uint32_t a0, a1, a2, a3;
            ldmx4(a0, a1, a2, a3, lmb + 32u * k);   // raw f32 bits -> tf32 (HW truncation)
            #pragma unroll
            for (int n = 0; n < 4; n++) {
                const uint2 bf = *(const uint2*)(smemA + W1F_OFF + (k * 4 + n) * 256 + lane * 8);
                mma8(d1[n], a0, a1, a2, a3, bf.x, bf.y);
            }
        }

        // ---- epilogue 1: h1 = f16x2(relu(d1)) at pair index p=4n+tig ----
        #pragma unroll
        for (int n = 0; n < 4; n++) {
            tu[r0 * S_TILE + 4 * n + tig] =
                pack_h2(fmaxf(d1[n][0], 0.0f), fmaxf(d1[n][1], 0.0f));
            tu[(r0 + 8) * S_TILE + 4 * n + tig] =
                pack_h2(fmaxf(d1[n][2], 0.0f), fmaxf(d1[n][3], 0.0f));
        }
        __syncwarp();

        // ---- layer 2: fp16 m16n8k16, D2[16x64], K=32 in 2 k-steps ----
        float d2[8][4];
        #pragma unroll
        for (int q = 0; q < 8; q++)
            #pragma unroll
            for (int c = 0; c < 4; c++) d2[q][c] = 0.0f;
        #pragma unroll
        for (int ks = 0; ks < 2; ks++) {
            uint32_t a0, a1, a2, a3;
            ldmx4(a0, a1, a2, a3, lmb + 32u * ks);  // h1 f16x2, ldmatrix-native
            #pragma unroll
            for (int q = 0; q < 8; q++) {
                const uint2 bf = *(const uint2*)(smemA + W2F_OFF + (ks * 8 + q) * 256 + lane * 8);
                mma16(d2[q], a0, a1, a2, a3, bf.x, bf.y);
            }
        }
        __syncthreads();   // all smem reads of this tile done; next issue may overwrite

        // ---- epilogue 2: relu(h2+b2) in regs ----
        float rA[16], rB[16];
        #pragma unroll
        for (int q = 0; q < 8; q++) {
            rA[2 * q]     = fmaxf(d2[q][0] + b2v0[q], 0.0f);
            rA[2 * q + 1] = fmaxf(d2[q][1] + b2v1[q], 0.0f);
            rB[2 * q]     = fmaxf(d2[q][2] + b2v0[q], 0.0f);
            rB[2 * q + 1] = fmaxf(d2[q][3] + b2v1[q], 0.0f);
        }

        // ---- warp-level segmented reduce: shfl over row-groups, REDG to g_acc ----
        // overlaps the cp.async fill of the next tile (no smem touched here)
        {
            bool doneA = (r0 >= nrows);
            bool doneB = (r0 + 8 >= nrows);
            while (true) {
                const int mysel = !doneA ? segA : (!doneB ? segB : 0x7fffffff);
                const int target = __reduce_min_sync(0xffffffffu, mysel);
                if (target == 0x7fffffff) break;
                const bool tA = !doneA && (segA == target);
                const bool tB = !doneB && (segB == target);
                float red[16];
                #pragma unroll
                for (int i = 0; i < 16; i++) {
                    red[i] = (tA ? rA[i] : 0.0f) + (tB ? rB[i] : 0.0f);
                    red[i] += __shfl_xor_sync(0xffffffffu, red[i], 4);
                    red[i] += __shfl_xor_sync(0xffffffffu, red[i], 8);
                    red[i] += __shfl_xor_sync(0xffffffffu, red[i], 16);
                }
                const unsigned ba = __ballot_sync(0xffffffffu, tA);
                const unsigned bb = __ballot_sync(0xffffffffu, tB);
                if (g < 2) {
                    float* dst = &g_acc[(size_t)target * 64];
                    #pragma unroll
                    for (int qq = 0; qq < 4; qq++) {
                        const int q = g * 4 + qq;
                        atomicAdd(dst + 8 * q + 2 * tig,     red[2 * q]);
                        atomicAdd(dst + 8 * q + 2 * tig + 1, red[2 * q + 1]);
                    }
                }
                if (lane == 0)
                    atomicAdd(&g_cnt[target],
                              0.25f * (float)(__popc(ba) + __popc(bb)));
                doneA = doneA || tA;
                doneB = doneB || tB;
            }
        }
        buf ^= 1;
    }
}

// ---------------- kernel B: per-segment mean @ W3 + b3 (W3 smem-cached) ----------------
#define SEG_PER_CTA 8
__global__ __launch_bounds__(128)
void seg_out_kernel(const float* __restrict__ W3, const float* __restrict__ b3,
                    float* __restrict__ out, int S)
{
    __shared__ float w3s[64 * 128];          // 32KB
    __shared__ float ms[SEG_PER_CTA][64];
    __shared__ float invs[SEG_PER_CTA];
    const int tid = threadIdx.x;
    const int s0  = blockIdx.x * SEG_PER_CTA;

    for (int i = tid; i < 64 * 128 / 4; i += 128)
        reinterpret_cast<float4*>(w3s)[i] = reinterpret_cast<const float4*>(W3)[i];
    for (int i = tid; i < SEG_PER_CTA * 64; i += 128)
        ms[i >> 6][i & 63] = g_acc[(size_t)s0 * 64 + i];
    if (tid < SEG_PER_CTA) {
        const float c = g_cnt[s0 + tid];
        invs[tid] = (c > 0.0f) ? (1.0f / c) : 0.0f;
    }
    __syncthreads();

    const float b3v = b3[tid];
    #pragma unroll
    for (int ss = 0; ss < SEG_PER_CTA; ss++) {
        if (s0 + ss >= S) break;
        const float inv = invs[ss];
        float res = 0.0f;
        if (inv > 0.0f) {
            float d = 0.0f;
            #pragma unroll 8
            for (int j = 0; j < 64; j++)
                d = fmaf(ms[ss][j] * inv, w3s[j * 128 + tid], d);
            res = d + b3v;
        }
        out[(size_t)(s0 + ss) * 128 + tid] = res;   // empty segment -> exact zeros
    }
}

extern "C" void kernel_launch(void* const* d_in, const int* in_sizes, int n_in,
                              void* d_out, int out_size) {
    // metadata order: f_all, seg_ids, num_segments, W1, b1, W2, b2, W3, b3
    const float* f_all   = (const float*)d_in[0];
    const int*   seg_ids = (const int*)  d_in[1];
    const float* W1      = (const float*)d_in[3];
    const float* b1      = (const float*)d_in[4];
    const float* W2      = (const float*)d_in[5];
    const float* b2      = (const float*)d_in[6];
    const float* W3      = (const float*)d_in[7];
    const float* b3      = (const float*)d_in[8];
    float* out = (float*)d_out;

    const int N = in_sizes[1];
    const int S = out_size / 128;

    // persistent grid = 2 CTAs per SM, queried from the device (no wave quantization)
    int dev = 0, sms = 148;
    cudaGetDevice(&dev);
    cudaDeviceGetAttribute(&sms, cudaDevAttrMultiProcessorCount, dev);
    const int grid_a = 2 * sms;

    cudaFuncSetAttribute(mlp_accum_kernel,
                         cudaFuncAttributeMaxDynamicSharedMemorySize, SMEM_A);

    const int zthreads = S * 16 + S / 4;
    zero_kernel<<<(zthreads + 255) / 256, 256>>>(S);
    mlp_accum_kernel<<<grid_a, TPB_A, SMEM_A>>>(f_all, seg_ids, N, W1, b1, W2, b2);
    seg_out_kernel<<<(S + SEG_PER_CTA - 1) / SEG_PER_CTA, 128>>>(W3, b3, out, S);
}